// round 4
// baseline (speedup 1.0000x reference)
#include <cuda_runtime.h>
#include <cuda_bf16.h>
#include <math.h>

#define N_NODES 4096
#define N_EDGES 8192
#define D       64
#define D3      67      // D + 3
#define F1      134     // 2*(D+3)
#define F2      201     // 3*(D+3)

// ---------------- device scratch (no allocation allowed) --------------------
__device__ int   g_seg_i[N_EDGES];
__device__ int   g_seg_o[N_EDGES];
__device__ __align__(16) float g_H0[N_NODES * D3];
__device__ __align__(16) float g_H1[N_NODES * D3];
__device__ __align__(16) float g_MI[N_NODES * D3];   // zero at load; re-zeroed by node phase
__device__ __align__(16) float g_MO[N_NODES * D3];

__device__ unsigned g_bar_count = 0;
__device__ volatile unsigned g_bar_gen = 0;

// ---------------- smem layout (floats) --------------------------------------
#define S_WE1 0                       // 134*64 = 8576  (k-major, float4 per 4 cols)
#define S_WN1 8576                    // 201*64 = 12864
#define S_WN2 (8576 + 12864)          // 21440 : 64*64 = 4096
#define S_BE1 (21440 + 4096)          // 25536 : 64
#define S_WE2 (S_BE1 + 64)            // 64
#define S_BN1 (S_WE2 + 64)            // 64
#define S_BN2 (S_BN1 + 64)            // 64
#define S_BUF (S_BN2 + 64)            // 25792
// edge tile: B^T [134][65]  = 8710
// node tile: M^T [201][33] = 6633  + h [32][66] = 2112  -> 8745
#define ET     64
#define EBSTR  65
#define NT     32
#define NMSTR  33
#define S_NH   (S_BUF + F2 * NMSTR)     // h buffer within union
#define S_EW   (S_BUF + 8745)           // 64
#define S_SI   (S_EW + 64)              // 64 ints
#define S_SO   (S_SI + 64)              // 64 ints
#define SMEM_FLOATS (S_SO + 64)         // 34937 floats = 139748 B

// ---------------- grid-wide barrier -----------------------------------------
__device__ __forceinline__ void grid_sync(int nblocks) {
    __syncthreads();
    if (threadIdx.x == 0) {
        __threadfence();
        unsigned gen = g_bar_gen;
        if (atomicAdd(&g_bar_count, 1u) == (unsigned)nblocks - 1u) {
            g_bar_count = 0u;
            __threadfence();
            g_bar_gen = gen + 1u;
        } else {
            while (g_bar_gen == gen) { __nanosleep(32); }
        }
        __threadfence();
    }
    __syncthreads();
}

// ---------------- phase 0: extract indices + input net ----------------------
__device__ __forceinline__ void ext_scan(const float* __restrict__ R,
                                         int* __restrict__ dst,
                                         unsigned base, unsigned stride) {
    const unsigned total4 = (unsigned)N_NODES * N_EDGES / 4;   // 8,388,608
    const float4* p = (const float4*)R;
    for (unsigned b = base; b < total4; b += stride) {
        float4 v0 = __ldcs(&p[b + 0]);
        float4 v1 = __ldcs(&p[b + 1]);
        float4 v2 = __ldcs(&p[b + 2]);
        float4 v3 = __ldcs(&p[b + 3]);
        unsigned g = b * 4u;
        int n = g >> 13;
        int e = g & (N_EDGES - 1);
        if (v0.x != 0.f) dst[e + 0]  = n;
        if (v0.y != 0.f) dst[e + 1]  = n;
        if (v0.z != 0.f) dst[e + 2]  = n;
        if (v0.w != 0.f) dst[e + 3]  = n;
        if (v1.x != 0.f) dst[e + 4]  = n;
        if (v1.y != 0.f) dst[e + 5]  = n;
        if (v1.z != 0.f) dst[e + 6]  = n;
        if (v1.w != 0.f) dst[e + 7]  = n;
        if (v2.x != 0.f) dst[e + 8]  = n;
        if (v2.y != 0.f) dst[e + 9]  = n;
        if (v2.z != 0.f) dst[e + 10] = n;
        if (v2.w != 0.f) dst[e + 11] = n;
        if (v3.x != 0.f) dst[e + 12] = n;
        if (v3.y != 0.f) dst[e + 13] = n;
        if (v3.z != 0.f) dst[e + 14] = n;
        if (v3.w != 0.f) dst[e + 15] = n;
    }
}
// NOTE: each thread handles 16 consecutive elements of one row (16 | 8192 so a
// 64B quad never crosses a row boundary; n,e derived from the quad start).

__device__ void extract_input_phase(const float* __restrict__ Ri,
                                    const float* __restrict__ Ro,
                                    const float* __restrict__ X,
                                    const float* __restrict__ W_in,
                                    const float* __restrict__ b_in,
                                    int nblocks) {
    unsigned base = (blockIdx.x * 1024u + threadIdx.x) * 4u;
    unsigned stride = (unsigned)nblocks * 4096u;
    ext_scan(Ri, g_seg_i, base, stride);
    ext_scan(Ro, g_seg_o, base, stride);
    for (int i = blockIdx.x * 1024 + threadIdx.x; i < N_NODES * D; i += nblocks * 1024) {
        int n = i >> 6, d = i & 63;
        float x0 = X[n * 3 + 0], x1 = X[n * 3 + 1], x2 = X[n * 3 + 2];
        float h = tanhf(x0 * W_in[d] + x1 * W_in[64 + d] + x2 * W_in[128 + d] + b_in[d]);
        g_H0[n * D3 + d] = h;
        if (d < 3) g_H0[n * D3 + D + d] = X[n * 3 + d];
    }
}

// ---------------- edge phase (+ optional fused scatter) ---------------------
// tile = 64 edges; B^T[k][j] k=0..133, j=0..63.  thread = 1 edge x 4 cols.
template<bool SCATTER>
__device__ void edge_phase(const float* __restrict__ H, float* __restrict__ out,
                           float be2s, float* sm, int nblocks) {
    int t = threadIdx.x;
    int* sSi = (int*)(sm + S_SI);
    int* sSo = (int*)(sm + S_SO);
    for (int tile = blockIdx.x; tile < N_EDGES / ET; tile += nblocks) {
        int e0 = tile * ET;
        if (t < ET) { sSi[t] = g_seg_i[e0 + t]; sSo[t] = g_seg_o[e0 + t]; }
        __syncthreads();
        // gather B^T: lanes walk k fast (coalesced H row reads), stride-65 smem
        for (int i = t; i < ET * F1; i += 1024) {
            int j = i / F1, k = i - j * F1;
            float v = (k < D3) ? H[sSo[j] * D3 + k] : H[sSi[j] * D3 + (k - D3)];
            sm[S_BUF + k * EBSTR + j] = v;
        }
        __syncthreads();
        {
            int cg = t & 15;          // 4 output cols
            int eg = t >> 4;          // edge 0..63
            const float4* W4 = (const float4*)(sm + S_WE1);
            const float* Bc = sm + S_BUF + eg;
            float4 A = ((const float4*)(sm + S_BE1))[cg];
            #pragma unroll 2
            for (int k = 0; k < F1; k++) {
                float4 w = W4[k * 16 + cg];
                float b = Bc[k * EBSTR];
                A.x += b * w.x; A.y += b * w.y; A.z += b * w.z; A.w += b * w.w;
            }
            float4 w2 = ((const float4*)(sm + S_WE2))[cg];
            float p = tanhf(A.x) * w2.x + tanhf(A.y) * w2.y
                    + tanhf(A.z) * w2.z + tanhf(A.w) * w2.w;
            #pragma unroll
            for (int off = 8; off; off >>= 1)
                p += __shfl_down_sync(0xffffffffu, p, off, 16);
            if (cg == 0) {
                float ew = 1.f / (1.f + __expf(-(p + be2s)));
                sm[S_EW + eg] = ew;
                if (!SCATTER) out[e0 + eg] = ew;
            }
        }
        __syncthreads();
        if (SCATTER) {
            for (int i = t; i < ET * D3; i += 1024) {
                int j = i / D3, k = i - j * D3;
                float ew = sm[S_EW + j];
                float bo = sm[S_BUF + k * EBSTR + j];
                float bi = sm[S_BUF + (k + D3) * EBSTR + j];
                atomicAdd(&g_MI[sSi[j] * D3 + k], ew * bo);
                atomicAdd(&g_MO[sSo[j] * D3 + k], ew * bi);
            }
            __syncthreads();
        }
    }
}

// ---------------- node phase (+ fused re-zero of MI/MO) ---------------------
// tile = 32 nodes; M^T[k][j] k=0..200, j=0..31.  thread = 1 node x 2 cols.
__device__ void node_phase(const float* __restrict__ Hin, float* __restrict__ Hout,
                           const float* __restrict__ X, float* sm, int nblocks) {
    int t = threadIdx.x;
    for (int tile = blockIdx.x; tile < N_NODES / NT; tile += nblocks) {
        int n0 = tile * NT;
        for (int i = t; i < NT * F2; i += 1024) {
            int j = i / F2, k = i - j * F2;
            int n = n0 + j;
            float v;
            if (k < D3)          v = g_MI[n * D3 + k];
            else if (k < 2 * D3) v = g_MO[n * D3 + (k - D3)];
            else                 v = Hin[n * D3 + (k - 2 * D3)];
            sm[S_BUF + k * NMSTR + j] = v;
        }
        __syncthreads();
        int cg = t & 31;          // cols 2cg, 2cg+1
        int ng = t >> 5;          // node 0..31
        {
            const float2* W2 = (const float2*)(sm + S_WN1);
            const float* Mc = sm + S_BUF + ng;
            float2 A = ((const float2*)(sm + S_BN1))[cg];
            #pragma unroll 3
            for (int k = 0; k < F2; k++) {
                float2 w = W2[k * 32 + cg];
                float b = Mc[k * NMSTR];
                A.x += b * w.x; A.y += b * w.y;
            }
            sm[S_NH + ng * 66 + 2 * cg + 0] = tanhf(A.x);
            sm[S_NH + ng * 66 + 2 * cg + 1] = tanhf(A.y);
        }
        __syncthreads();
        {
            const float2* W2 = (const float2*)(sm + S_WN2);
            const float* hh = sm + S_NH + ng * 66;
            float2 A = ((const float2*)(sm + S_BN2))[cg];
            #pragma unroll 4
            for (int k = 0; k < D; k++) {
                float2 w = W2[k * 32 + cg];
                float h = hh[k];
                A.x += h * w.x; A.y += h * w.y;
            }
            int n = n0 + ng;
            Hout[n * D3 + 2 * cg + 0] = 1.f / (1.f + __expf(-A.x));
            Hout[n * D3 + 2 * cg + 1] = 1.f / (1.f + __expf(-A.y));
            if (t < NT * 3) {
                int j = t / 3, c = t - j * 3;
                Hout[(n0 + j) * D3 + D + c] = X[(n0 + j) * 3 + c];
            }
        }
        // re-zero MI/MO for this tile
        for (int i = t; i < NT * D3; i += 1024) {
            int j = i / D3, k = i - j * D3;
            g_MI[(n0 + j) * D3 + k] = 0.f;
            g_MO[(n0 + j) * D3 + k] = 0.f;
        }
        __syncthreads();
    }
}

// ---------------- persistent kernel ------------------------------------------
__global__ void __launch_bounds__(1024, 1)
gnn_persistent(const float* __restrict__ X,
               const float* __restrict__ Ri,  const float* __restrict__ Ro,
               const float* __restrict__ W_in, const float* __restrict__ b_in,
               const float* __restrict__ We1, const float* __restrict__ be1,
               const float* __restrict__ We2, const float* __restrict__ be2,
               const float* __restrict__ Wn1, const float* __restrict__ bn1,
               const float* __restrict__ Wn2, const float* __restrict__ bn2,
               float* __restrict__ out, int nblocks) {
    extern __shared__ float sm[];
    int t = threadIdx.x;
    for (int i = t; i < F1 * D; i += 1024) sm[S_WE1 + i] = We1[i];
    for (int i = t; i < F2 * D; i += 1024) sm[S_WN1 + i] = Wn1[i];
    for (int i = t; i < D * D;  i += 1024) sm[S_WN2 + i] = Wn2[i];
    if (t < 64) {
        sm[S_BE1 + t] = be1[t];
        sm[S_WE2 + t] = We2[t];
        sm[S_BN1 + t] = bn1[t];
        sm[S_BN2 + t] = bn2[t];
    }
    float be2s = be2[0];

    extract_input_phase(Ri, Ro, X, W_in, b_in, nblocks);
    grid_sync(nblocks);

    float* Hc = g_H0;
    float* Hn = g_H1;
    #pragma unroll 1
    for (int it = 0; it < 3; it++) {
        edge_phase<true>(Hc, nullptr, be2s, sm, nblocks);
        grid_sync(nblocks);
        node_phase(Hc, Hn, X, sm, nblocks);
        grid_sync(nblocks);
        float* tmp = Hc; Hc = Hn; Hn = tmp;
    }
    edge_phase<false>(Hc, out, be2s, sm, nblocks);
}

// ---------------- launcher ----------------------------------------------------
extern "C" void kernel_launch(void* const* d_in, const int* in_sizes, int n_in,
                              void* d_out, int out_size) {
    const float* X    = (const float*)d_in[0];
    const float* Ri   = (const float*)d_in[1];
    const float* Ro   = (const float*)d_in[2];
    const float* W_in = (const float*)d_in[3];
    const float* b_in = (const float*)d_in[4];
    const float* We1  = (const float*)d_in[5];
    const float* be1  = (const float*)d_in[6];
    const float* We2  = (const float*)d_in[7];
    const float* be2  = (const float*)d_in[8];
    const float* Wn1  = (const float*)d_in[9];
    const float* bn1  = (const float*)d_in[10];
    const float* Wn2  = (const float*)d_in[11];
    const float* bn2  = (const float*)d_in[12];
    float* out = (float*)d_out;

    int dev = 0, nsm = 0;
    cudaGetDevice(&dev);
    cudaDeviceGetAttribute(&nsm, cudaDevAttrMultiProcessorCount, dev);

    cudaFuncSetAttribute(gnn_persistent, cudaFuncAttributeMaxDynamicSharedMemorySize,
                         SMEM_FLOATS * 4);

    gnn_persistent<<<nsm, 1024, SMEM_FLOATS * 4>>>(
        X, Ri, Ro, W_in, b_in, We1, be1, We2, be2, Wn1, bn1, Wn2, bn2, out, nsm);
}